// round 2
// baseline (speedup 1.0000x reference)
#include <cuda_runtime.h>
#include <cuda_bf16.h>
#include <math.h>
#include <stdint.h>

// ---------------- problem constants ----------------
#define B_   2
#define S_   4096
#define DM_  768
#define DI_  1152
#define H_   12
#define DH_  64
#define ROWS (B_ * S_)          // 8192
#define DQKV (3 * DM_)          // 2304
#define WIN  64                 // WINDOW/2

// ---------------- scratch (no cudaMalloc allowed) ----------------
__device__ float g_h[ROWS * DM_];
__device__ float g_qkv[ROWS * DQKV];
__device__ float g_attn[ROWS * DM_];
__device__ float g_x1[ROWS * DM_];
__device__ float g_gate[ROWS * DI_];
__device__ float g_up[ROWS * DI_];

// ---------------- TF32 rounding (matches tensor-core input rounding) --------
__device__ __forceinline__ float tf32r(float x) {
    uint32_t u;
    asm("cvt.rna.tf32.f32 %0, %1;" : "=r"(u) : "f"(x));
    return __uint_as_float(u);
}

// ---------------- reductions ----------------
__device__ __forceinline__ float warpMax(float v) {
    #pragma unroll
    for (int o = 16; o; o >>= 1) v = fmaxf(v, __shfl_xor_sync(0xffffffffu, v, o));
    return v;
}
__device__ __forceinline__ float warpSum(float v) {
    #pragma unroll
    for (int o = 16; o; o >>= 1) v += __shfl_xor_sync(0xffffffffu, v, o);
    return v;
}

// ---------------- RMSNorm ----------------
__global__ void rmsnorm_kernel(const float* __restrict__ x,
                               const float* __restrict__ gamma,
                               float* __restrict__ o) {
    int row = blockIdx.x;
    const float* xr = x + (size_t)row * DM_;
    float s = 0.f;
    for (int i = threadIdx.x; i < DM_; i += 256) { float v = xr[i]; s += v * v; }
    __shared__ float red[8];
    float w = warpSum(s);
    if ((threadIdx.x & 31) == 0) red[threadIdx.x >> 5] = w;
    __syncthreads();
    float tot = 0.f;
    #pragma unroll
    for (int i = 0; i < 8; i++) tot += red[i];
    float inv = rsqrtf(tot / (float)DM_ + 1e-5f);
    float* orow = o + (size_t)row * DM_;
    for (int i = threadIdx.x; i < DM_; i += 256) orow[i] = xr[i] * inv * gamma[i];
}

// ---------------- SGEMM 128x128x8, 8x8/thread, TF32-rounded operands --------
#define BM 128
#define BN 128
#define BK 8
__global__ __launch_bounds__(256, 2)
void sgemm_kernel(const float* __restrict__ A, const float* __restrict__ Bm,
                  const float* __restrict__ Res, float* __restrict__ C,
                  int M, int N, int K, int addRes) {
    __shared__ float As[BK][BM];
    __shared__ float Bs[BK][BN];
    int tid = threadIdx.x;
    int bm = blockIdx.y * BM;
    int bn = blockIdx.x * BN;

    int arow = tid >> 1;
    int acol = (tid & 1) * 4;
    int brow = tid >> 5;
    int bcol = (tid & 31) * 4;

    int tx = tid & 15;
    int ty = tid >> 4;

    float acc[8][8];
    #pragma unroll
    for (int i = 0; i < 8; i++)
        #pragma unroll
        for (int j = 0; j < 8; j++) acc[i][j] = 0.f;

    const float* Aptr = A + (size_t)(bm + arow) * K + acol;
    const float* Bptr = Bm + (size_t)brow * N + bn + bcol;

    for (int k0 = 0; k0 < K; k0 += BK) {
        float4 av = *(const float4*)(Aptr + k0);
        As[acol + 0][arow] = tf32r(av.x);
        As[acol + 1][arow] = tf32r(av.y);
        As[acol + 2][arow] = tf32r(av.z);
        As[acol + 3][arow] = tf32r(av.w);
        float4 bv = *(const float4*)(Bptr + (size_t)k0 * N);
        bv.x = tf32r(bv.x); bv.y = tf32r(bv.y);
        bv.z = tf32r(bv.z); bv.w = tf32r(bv.w);
        *(float4*)&Bs[brow][bcol] = bv;
        __syncthreads();
        #pragma unroll
        for (int k = 0; k < BK; ++k) {
            float ar[8], br[8];
            #pragma unroll
            for (int i = 0; i < 4; i++) {
                ar[i]     = As[k][ty * 4 + i];
                ar[4 + i] = As[k][64 + ty * 4 + i];
                br[i]     = Bs[k][tx * 4 + i];
                br[4 + i] = Bs[k][64 + tx * 4 + i];
            }
            #pragma unroll
            for (int i = 0; i < 8; i++)
                #pragma unroll
                for (int j = 0; j < 8; j++)
                    acc[i][j] += ar[i] * br[j];
        }
        __syncthreads();
    }

    #pragma unroll
    for (int i = 0; i < 8; i++) {
        int m = bm + ((i < 4) ? (ty * 4 + i) : (64 + ty * 4 + (i - 4)));
        #pragma unroll
        for (int jq = 0; jq < 2; jq++) {
            int n = bn + ((jq == 0) ? (tx * 4) : (64 + tx * 4));
            float4 v;
            v.x = acc[i][jq * 4 + 0];
            v.y = acc[i][jq * 4 + 1];
            v.z = acc[i][jq * 4 + 2];
            v.w = acc[i][jq * 4 + 3];
            if (addRes) {
                float4 r = *(const float4*)(Res + (size_t)m * N + n);
                v.x += r.x; v.y += r.y; v.z += r.z; v.w += r.w;
            }
            *(float4*)(C + (size_t)m * N + n) = v;
        }
    }
}

// ---------------- RoPE (mirrors reference fp32 path exactly) ----------------
__global__ void rope_kernel(float* __restrict__ qkv) {
    int idx = blockIdx.x * blockDim.x + threadIdx.x;
    const int total = B_ * S_ * 2 * H_ * (DH_ / 2);
    if (idx >= total) return;
    int d = idx & 31; idx >>= 5;
    int h = idx % H_; idx /= H_;
    int e = idx & 1;  idx >>= 1;
    int s = idx % S_;
    int b = idx / S_;
    // reference: inv_freq = 1.0 / 10000.0 ** ((2d)/64)  (all fp32)
    float w = (float)(2 * d) / (float)DH_;
    float inv_freq = 1.0f / powf(10000.0f, w);
    float ang = (float)s * inv_freq;
    float cs = cosf(ang);
    float sn = sinf(ang);
    size_t base = (size_t)(b * S_ + s) * DQKV + e * DM_ + h * DH_;
    float x1 = qkv[base + d];
    float x2 = qkv[base + d + 32];
    qkv[base + d]      = x1 * cs - x2 * sn;
    qkv[base + d + 32] = x2 * cs + x1 * sn;
}

// ---------------- sliding-window attention (TF32 dots) ----------------
__global__ __launch_bounds__(128)
void attn_kernel(const float* __restrict__ qkv, const int* __restrict__ pmask,
                 float* __restrict__ out) {
    int qi = blockIdx.x;
    int h  = blockIdx.y;
    int b  = blockIdx.z;
    int tid = threadIdx.x;

    __shared__ float qs[DH_];
    __shared__ float sc[132];
    __shared__ float red[4];

    size_t rowq = (size_t)(b * S_ + qi) * DQKV;
    if (tid < DH_) qs[tid] = tf32r(qkv[rowq + h * DH_ + tid]);
    int jlo = max(qi - WIN, 0);
    int jhi = min(qi + WIN, S_ - 1);
    int nk = jhi - jlo + 1;
    __syncthreads();

    float lmax = -1e30f;
    for (int jj = tid; jj < nk; jj += 128) {
        int j = jlo + jj;
        const float4* kp = (const float4*)&qkv[(size_t)(b * S_ + j) * DQKV + DM_ + h * DH_];
        float d = 0.f;
        #pragma unroll
        for (int t = 0; t < DH_ / 4; t++) {
            float4 kv = kp[t];
            d += qs[4 * t + 0] * tf32r(kv.x) + qs[4 * t + 1] * tf32r(kv.y)
               + qs[4 * t + 2] * tf32r(kv.z) + qs[4 * t + 3] * tf32r(kv.w);
        }
        d *= 0.125f;  // / sqrt(64)
        if (pmask[b * S_ + j] == 0) d -= 10000.0f;
        sc[jj] = d;
        lmax = fmaxf(lmax, d);
    }

    float m = warpMax(lmax);
    if ((tid & 31) == 0) red[tid >> 5] = m;
    __syncthreads();
    float gmax = fmaxf(fmaxf(red[0], red[1]), fmaxf(red[2], red[3]));
    __syncthreads();

    float lsum = 0.f;
    for (int jj = tid; jj < nk; jj += 128) {
        float p = expf(sc[jj] - gmax);
        sc[jj] = p;
        lsum += p;
    }
    float ws = warpSum(lsum);
    __syncthreads();
    if ((tid & 31) == 0) red[tid >> 5] = ws;
    __syncthreads();
    float gsum = red[0] + red[1] + red[2] + red[3];

    // normalize + TF32-round probabilities (reference: softmax -> TF32 einsum)
    for (int jj = tid; jj < nk; jj += 128) sc[jj] = tf32r(sc[jj] / gsum);
    __syncthreads();

    if (tid < DH_) {
        float o = 0.f;
        #pragma unroll 4
        for (int jj = 0; jj < nk; jj++) {
            int j = jlo + jj;
            o += sc[jj] * tf32r(qkv[(size_t)(b * S_ + j) * DQKV + 2 * DM_ + h * DH_ + tid]);
        }
        out[(size_t)(b * S_ + qi) * DM_ + h * DH_ + tid] = o;
    }
}

// ---------------- gelu(gate) * up ----------------
__global__ void gelumul_kernel(float* __restrict__ g, const float* __restrict__ u, int n) {
    int i = blockIdx.x * blockDim.x + threadIdx.x;
    if (i >= n) return;
    float x = g[i];
    float t = tanhf(0.7978845608028654f * (x + 0.044715f * x * x * x));
    g[i] = 0.5f * x * (1.0f + t) * u[i];
}

// ---------------- launch ----------------
extern "C" void kernel_launch(void* const* d_in, const int* in_sizes, int n_in,
                              void* d_out, int out_size) {
    const float* x          = (const float*)d_in[0];
    const int*   pmask      = (const int*)  d_in[1];
    const float* w_qkv      = (const float*)d_in[2];
    const float* w_o        = (const float*)d_in[3];
    const float* gamma_attn = (const float*)d_in[4];
    const float* gamma_mlp  = (const float*)d_in[5];
    const float* w_i0       = (const float*)d_in[6];
    const float* w_i1       = (const float*)d_in[7];
    const float* w_mo       = (const float*)d_in[8];
    float* out = (float*)d_out;

    float *h, *qkv, *attn, *x1, *gate, *up;
    cudaGetSymbolAddress((void**)&h,    g_h);
    cudaGetSymbolAddress((void**)&qkv,  g_qkv);
    cudaGetSymbolAddress((void**)&attn, g_attn);
    cudaGetSymbolAddress((void**)&x1,   g_x1);
    cudaGetSymbolAddress((void**)&gate, g_gate);
    cudaGetSymbolAddress((void**)&up,   g_up);

    rmsnorm_kernel<<<ROWS, 256>>>(x, gamma_attn, h);
    sgemm_kernel<<<dim3(DQKV / BN, ROWS / BM), 256>>>(h, w_qkv, nullptr, qkv, ROWS, DQKV, DM_, 0);
    {
        int total = B_ * S_ * 2 * H_ * (DH_ / 2);
        rope_kernel<<<(total + 255) / 256, 256>>>(qkv);
    }
    attn_kernel<<<dim3(S_, H_, B_), 128>>>(qkv, pmask, attn);
    sgemm_kernel<<<dim3(DM_ / BN, ROWS / BM), 256>>>(attn, w_o, x, x1, ROWS, DM_, DM_, 1);
    rmsnorm_kernel<<<ROWS, 256>>>(x1, gamma_mlp, h);
    sgemm_kernel<<<dim3(DI_ / BN, ROWS / BM), 256>>>(h, w_i0, nullptr, gate, ROWS, DI_, DM_, 0);
    sgemm_kernel<<<dim3(DI_ / BN, ROWS / BM), 256>>>(h, w_i1, nullptr, up,   ROWS, DI_, DM_, 0);
    {
        int n = ROWS * DI_;
        gelumul_kernel<<<(n + 255) / 256, 256>>>(gate, up, n);
    }
    sgemm_kernel<<<dim3(DM_ / BN, ROWS / BM), 256>>>(gate, w_mo, x1, out, ROWS, DM_, DI_, 1);
}

// round 3
// speedup vs baseline: 1.4562x; 1.4562x over previous
#include <cuda_runtime.h>
#include <cuda_bf16.h>
#include <math.h>
#include <stdint.h>

// ---------------- problem constants ----------------
#define B_   2
#define S_   4096
#define DM_  768
#define DI_  1152
#define H_   12
#define DH_  64
#define ROWS (B_ * S_)          // 8192
#define DQKV (3 * DM_)          // 2304
#define WIN  64                 // WINDOW/2

// ---------------- scratch ----------------
__device__ float g_h[ROWS * DM_];
__device__ float g_qkv[ROWS * DQKV];
__device__ float g_attn[ROWS * DM_];
__device__ float g_x1[ROWS * DM_];
__device__ float g_gate[ROWS * DI_];
__device__ float g_up[ROWS * DI_];

// ---------------- TF32 rounding ----------------
__device__ __forceinline__ float tf32r(float x) {
    uint32_t u;
    asm("cvt.rna.tf32.f32 %0, %1;" : "=r"(u) : "f"(x));
    return __uint_as_float(u);
}

__device__ __forceinline__ float warpMax(float v) {
    #pragma unroll
    for (int o = 16; o; o >>= 1) v = fmaxf(v, __shfl_xor_sync(0xffffffffu, v, o));
    return v;
}
__device__ __forceinline__ float warpSum(float v) {
    #pragma unroll
    for (int o = 16; o; o >>= 1) v += __shfl_xor_sync(0xffffffffu, v, o);
    return v;
}

// ---------------- RMSNorm ----------------
__global__ void rmsnorm_kernel(const float* __restrict__ x,
                               const float* __restrict__ gamma,
                               float* __restrict__ o) {
    int row = blockIdx.x;
    const float* xr = x + (size_t)row * DM_;
    float s = 0.f;
    for (int i = threadIdx.x; i < DM_; i += 256) { float v = xr[i]; s += v * v; }
    __shared__ float red[8];
    float w = warpSum(s);
    if ((threadIdx.x & 31) == 0) red[threadIdx.x >> 5] = w;
    __syncthreads();
    float tot = 0.f;
    #pragma unroll
    for (int i = 0; i < 8; i++) tot += red[i];
    float inv = rsqrtf(tot / (float)DM_ + 1e-5f);
    float* orow = o + (size_t)row * DM_;
    for (int i = threadIdx.x; i < DM_; i += 256) orow[i] = xr[i] * inv * gamma[i];
}

// =================== TF32 tensor-core GEMM ===================
// C[M,N] = A[M,K] @ B[K,N] (+ Res). Tiles 128x128x32, 256 thr, 8 warps.
// Warp = 32x64 via m16n8k8 (2 m-tiles x 8 n-tiles).
#define BM 128
#define BN 128
#define BK 32
#define ASTRIDE 36   // 128x36 floats, (row*36+col)%32 = (4*row+col)%32 -> frag LDS conflict-free
#define BSTRIDE 136  // 32x136 floats, (8*row+col)%32 -> frag LDS conflict-free
#define STAGE_FLOATS (BM * ASTRIDE + BK * BSTRIDE)   // 8960
#define GEMM_SMEM_BYTES (2 * STAGE_FLOATS * 4)        // 71680

__device__ __forceinline__ void mma_tf32(float c[4], const uint32_t a[4], const uint32_t b[2]) {
    asm volatile(
        "mma.sync.aligned.m16n8k8.row.col.f32.tf32.tf32.f32 "
        "{%0,%1,%2,%3}, {%4,%5,%6,%7}, {%8,%9}, {%0,%1,%2,%3};"
        : "+f"(c[0]), "+f"(c[1]), "+f"(c[2]), "+f"(c[3])
        : "r"(a[0]), "r"(a[1]), "r"(a[2]), "r"(a[3]), "r"(b[0]), "r"(b[1]));
}

__global__ __launch_bounds__(256, 1)
void mma_gemm_kernel(const float* __restrict__ A, const float* __restrict__ Bg,
                     const float* __restrict__ Res, float* __restrict__ C,
                     int M, int N, int K, int addRes) {
    extern __shared__ float smem[];
    float* stage[2] = { smem, smem + STAGE_FLOATS };

    const int tid  = threadIdx.x;
    const int lane = tid & 31;
    const int warp = tid >> 5;
    const int gid  = lane >> 2;   // 0..7
    const int tg   = lane & 3;    // 0..3
    const int wm   = warp >> 1;   // 0..3
    const int wn   = warp & 1;    // 0..1

    const int bm = blockIdx.y * BM;
    const int bn = blockIdx.x * BN;

    // staging indices
    const int arow = tid >> 3;         // 0..31
    const int acol = (tid & 7) * 4;    // 0..28
    const int brow = tid >> 5;         // 0..7
    const int bcol = (tid & 31) * 4;   // 0..124

    float acc[2][8][4];
    #pragma unroll
    for (int i = 0; i < 2; i++)
        #pragma unroll
        for (int j = 0; j < 8; j++)
            #pragma unroll
            for (int l = 0; l < 4; l++) acc[i][j][l] = 0.f;

    const int ntiles = K / BK;

    float4 ar[4], br[4];
    // prologue: load tile 0
    #pragma unroll
    for (int i = 0; i < 4; i++)
        ar[i] = *(const float4*)&A[(size_t)(bm + arow + 32 * i) * K + acol];
    #pragma unroll
    for (int i = 0; i < 4; i++)
        br[i] = *(const float4*)&Bg[(size_t)(brow + 8 * i) * N + bn + bcol];

    {
        float* As = stage[0];
        float* Bs = stage[0] + BM * ASTRIDE;
        #pragma unroll
        for (int i = 0; i < 4; i++) {
            float4 v = ar[i];
            v.x = tf32r(v.x); v.y = tf32r(v.y); v.z = tf32r(v.z); v.w = tf32r(v.w);
            *(float4*)&As[(arow + 32 * i) * ASTRIDE + acol] = v;
        }
        #pragma unroll
        for (int i = 0; i < 4; i++) {
            float4 v = br[i];
            v.x = tf32r(v.x); v.y = tf32r(v.y); v.z = tf32r(v.z); v.w = tf32r(v.w);
            *(float4*)&Bs[(brow + 8 * i) * BSTRIDE + bcol] = v;
        }
    }
    __syncthreads();

    int cur = 0;
    for (int t = 0; t < ntiles; t++) {
        // prefetch next tile into regs
        if (t + 1 < ntiles) {
            int k0 = (t + 1) * BK;
            #pragma unroll
            for (int i = 0; i < 4; i++)
                ar[i] = *(const float4*)&A[(size_t)(bm + arow + 32 * i) * K + k0 + acol];
            #pragma unroll
            for (int i = 0; i < 4; i++)
                br[i] = *(const float4*)&Bg[(size_t)(k0 + brow + 8 * i) * N + bn + bcol];
        }

        const float* As = stage[cur];
        const float* Bs = stage[cur] + BM * ASTRIDE;

        #pragma unroll
        for (int ks = 0; ks < 4; ks++) {
            uint32_t af[2][4], bf[8][2];
            int col = ks * 8 + tg;
            #pragma unroll
            for (int mt = 0; mt < 2; mt++) {
                int r = wm * 32 + mt * 16 + gid;
                af[mt][0] = __float_as_uint(As[r * ASTRIDE + col]);
                af[mt][1] = __float_as_uint(As[(r + 8) * ASTRIDE + col]);
                af[mt][2] = __float_as_uint(As[r * ASTRIDE + col + 4]);
                af[mt][3] = __float_as_uint(As[(r + 8) * ASTRIDE + col + 4]);
            }
            #pragma unroll
            for (int nt = 0; nt < 8; nt++) {
                int c = wn * 64 + nt * 8 + gid;
                bf[nt][0] = __float_as_uint(Bs[(ks * 8 + tg) * BSTRIDE + c]);
                bf[nt][1] = __float_as_uint(Bs[(ks * 8 + tg + 4) * BSTRIDE + c]);
            }
            #pragma unroll
            for (int mt = 0; mt < 2; mt++)
                #pragma unroll
                for (int nt = 0; nt < 8; nt++)
                    mma_tf32(acc[mt][nt], af[mt], bf[nt]);
        }

        // stage next tile
        if (t + 1 < ntiles) {
            float* As2 = stage[cur ^ 1];
            float* Bs2 = stage[cur ^ 1] + BM * ASTRIDE;
            #pragma unroll
            for (int i = 0; i < 4; i++) {
                float4 v = ar[i];
                v.x = tf32r(v.x); v.y = tf32r(v.y); v.z = tf32r(v.z); v.w = tf32r(v.w);
                *(float4*)&As2[(arow + 32 * i) * ASTRIDE + acol] = v;
            }
            #pragma unroll
            for (int i = 0; i < 4; i++) {
                float4 v = br[i];
                v.x = tf32r(v.x); v.y = tf32r(v.y); v.z = tf32r(v.z); v.w = tf32r(v.w);
                *(float4*)&Bs2[(brow + 8 * i) * BSTRIDE + bcol] = v;
            }
            __syncthreads();
            cur ^= 1;
        }
    }

    // epilogue: c0 -> (gid, tg*2), c1 -> (gid, tg*2+1), c2/c3 -> row+8
    #pragma unroll
    for (int mt = 0; mt < 2; mt++) {
        #pragma unroll
        for (int nt = 0; nt < 8; nt++) {
            int m0 = bm + wm * 32 + mt * 16 + gid;
            int n0 = bn + wn * 64 + nt * 8 + tg * 2;
            float2 v0 = make_float2(acc[mt][nt][0], acc[mt][nt][1]);
            float2 v1 = make_float2(acc[mt][nt][2], acc[mt][nt][3]);
            if (addRes) {
                float2 r0 = *(const float2*)&Res[(size_t)m0 * N + n0];
                float2 r1 = *(const float2*)&Res[(size_t)(m0 + 8) * N + n0];
                v0.x += r0.x; v0.y += r0.y;
                v1.x += r1.x; v1.y += r1.y;
            }
            *(float2*)&C[(size_t)m0 * N + n0] = v0;
            *(float2*)&C[(size_t)(m0 + 8) * N + n0] = v1;
        }
    }
}

// ---------------- RoPE ----------------
__global__ void rope_kernel(float* __restrict__ qkv) {
    int idx = blockIdx.x * blockDim.x + threadIdx.x;
    const int total = B_ * S_ * 2 * H_ * (DH_ / 2);
    if (idx >= total) return;
    int d = idx & 31; idx >>= 5;
    int h = idx % H_; idx /= H_;
    int e = idx & 1;  idx >>= 1;
    int s = idx % S_;
    int b = idx / S_;
    float w = (float)(2 * d) / (float)DH_;
    float inv_freq = 1.0f / powf(10000.0f, w);
    float ang = (float)s * inv_freq;
    float cs = cosf(ang);
    float sn = sinf(ang);
    size_t base = (size_t)(b * S_ + s) * DQKV + e * DM_ + h * DH_;
    float x1 = qkv[base + d];
    float x2 = qkv[base + d + 32];
    qkv[base + d]      = x1 * cs - x2 * sn;
    qkv[base + d + 32] = x2 * cs + x1 * sn;
}

// ---------------- sliding-window attention ----------------
__global__ __launch_bounds__(128)
void attn_kernel(const float* __restrict__ qkv, const int* __restrict__ pmask,
                 float* __restrict__ out) {
    int qi = blockIdx.x;
    int h  = blockIdx.y;
    int b  = blockIdx.z;
    int tid = threadIdx.x;

    __shared__ float qs[DH_];
    __shared__ float sc[132];
    __shared__ float red[4];

    size_t rowq = (size_t)(b * S_ + qi) * DQKV;
    if (tid < DH_) qs[tid] = tf32r(qkv[rowq + h * DH_ + tid]);
    int jlo = max(qi - WIN, 0);
    int jhi = min(qi + WIN, S_ - 1);
    int nk = jhi - jlo + 1;
    __syncthreads();

    float lmax = -1e30f;
    for (int jj = tid; jj < nk; jj += 128) {
        int j = jlo + jj;
        const float4* kp = (const float4*)&qkv[(size_t)(b * S_ + j) * DQKV + DM_ + h * DH_];
        float d = 0.f;
        #pragma unroll
        for (int t = 0; t < DH_ / 4; t++) {
            float4 kv = kp[t];
            d += qs[4 * t + 0] * tf32r(kv.x) + qs[4 * t + 1] * tf32r(kv.y)
               + qs[4 * t + 2] * tf32r(kv.z) + qs[4 * t + 3] * tf32r(kv.w);
        }
        d *= 0.125f;
        if (pmask[b * S_ + j] == 0) d -= 10000.0f;
        sc[jj] = d;
        lmax = fmaxf(lmax, d);
    }

    float m = warpMax(lmax);
    if ((tid & 31) == 0) red[tid >> 5] = m;
    __syncthreads();
    float gmax = fmaxf(fmaxf(red[0], red[1]), fmaxf(red[2], red[3]));
    __syncthreads();

    float lsum = 0.f;
    for (int jj = tid; jj < nk; jj += 128) {
        float p = expf(sc[jj] - gmax);
        sc[jj] = p;
        lsum += p;
    }
    float ws = warpSum(lsum);
    __syncthreads();
    if ((tid & 31) == 0) red[tid >> 5] = ws;
    __syncthreads();
    float gsum = red[0] + red[1] + red[2] + red[3];

    for (int jj = tid; jj < nk; jj += 128) sc[jj] = tf32r(sc[jj] / gsum);
    __syncthreads();

    if (tid < DH_) {
        float o = 0.f;
        #pragma unroll 4
        for (int jj = 0; jj < nk; jj++) {
            int j = jlo + jj;
            o += sc[jj] * tf32r(qkv[(size_t)(b * S_ + j) * DQKV + 2 * DM_ + h * DH_ + tid]);
        }
        out[(size_t)(b * S_ + qi) * DM_ + h * DH_ + tid] = o;
    }
}

// ---------------- gelu(gate) * up ----------------
__global__ void gelumul_kernel(float* __restrict__ g, const float* __restrict__ u, int n) {
    int i = blockIdx.x * blockDim.x + threadIdx.x;
    if (i >= n) return;
    float x = g[i];
    float t = tanhf(0.7978845608028654f * (x + 0.044715f * x * x * x));
    g[i] = 0.5f * x * (1.0f + t) * u[i];
}

// ---------------- launch ----------------
extern "C" void kernel_launch(void* const* d_in, const int* in_sizes, int n_in,
                              void* d_out, int out_size) {
    const float* x          = (const float*)d_in[0];
    const int*   pmask      = (const int*)  d_in[1];
    const float* w_qkv      = (const float*)d_in[2];
    const float* w_o        = (const float*)d_in[3];
    const float* gamma_attn = (const float*)d_in[4];
    const float* gamma_mlp  = (const float*)d_in[5];
    const float* w_i0       = (const float*)d_in[6];
    const float* w_i1       = (const float*)d_in[7];
    const float* w_mo       = (const float*)d_in[8];
    float* out = (float*)d_out;

    float *h, *qkv, *attn, *x1, *gate, *up;
    cudaGetSymbolAddress((void**)&h,    g_h);
    cudaGetSymbolAddress((void**)&qkv,  g_qkv);
    cudaGetSymbolAddress((void**)&attn, g_attn);
    cudaGetSymbolAddress((void**)&x1,   g_x1);
    cudaGetSymbolAddress((void**)&gate, g_gate);
    cudaGetSymbolAddress((void**)&up,   g_up);

    cudaFuncSetAttribute(mma_gemm_kernel,
                         cudaFuncAttributeMaxDynamicSharedMemorySize, GEMM_SMEM_BYTES);

    rmsnorm_kernel<<<ROWS, 256>>>(x, gamma_attn, h);
    mma_gemm_kernel<<<dim3(DQKV / BN, ROWS / BM), 256, GEMM_SMEM_BYTES>>>(
        h, w_qkv, nullptr, qkv, ROWS, DQKV, DM_, 0);
    {
        int total = B_ * S_ * 2 * H_ * (DH_ / 2);
        rope_kernel<<<(total + 255) / 256, 256>>>(qkv);
    }
    attn_kernel<<<dim3(S_, H_, B_), 128>>>(qkv, pmask, attn);
    mma_gemm_kernel<<<dim3(DM_ / BN, ROWS / BM), 256, GEMM_SMEM_BYTES>>>(
        attn, w_o, x, x1, ROWS, DM_, DM_, 1);
    rmsnorm_kernel<<<ROWS, 256>>>(x1, gamma_mlp, h);
    mma_gemm_kernel<<<dim3(DI_ / BN, ROWS / BM), 256, GEMM_SMEM_BYTES>>>(
        h, w_i0, nullptr, gate, ROWS, DI_, DM_, 0);
    mma_gemm_kernel<<<dim3(DI_ / BN, ROWS / BM), 256, GEMM_SMEM_BYTES>>>(
        h, w_i1, nullptr, up, ROWS, DI_, DM_, 0);
    {
        int n = ROWS * DI_;
        gelumul_kernel<<<(n + 255) / 256, 256>>>(gate, up, n);
    }
    mma_gemm_kernel<<<dim3(DM_ / BN, ROWS / BM), 256, GEMM_SMEM_BYTES>>>(
        gate, w_mo, x1, out, ROWS, DM_, DI_, 1);
}

// round 4
// speedup vs baseline: 2.4320x; 1.6702x over previous
#include <cuda_runtime.h>
#include <cuda_bf16.h>
#include <math.h>
#include <stdint.h>

// ---------------- problem constants ----------------
#define B_   2
#define S_   4096
#define DM_  768
#define DI_  1152
#define H_   12
#define DH_  64
#define ROWS (B_ * S_)          // 8192
#define DQKV (3 * DM_)          // 2304
#define WIN  64                 // WINDOW/2

// ---------------- scratch ----------------
__device__ float g_h[ROWS * DM_];
__device__ float g_qkv[ROWS * DQKV];
__device__ float g_attn[ROWS * DM_];
__device__ float g_x1[ROWS * DM_];
__device__ float g_gate[ROWS * DI_];
__device__ float g_up[ROWS * DI_];

// ---------------- TF32 rounding ----------------
__device__ __forceinline__ float tf32r(float x) {
    uint32_t u;
    asm("cvt.rna.tf32.f32 %0, %1;" : "=r"(u) : "f"(x));
    return __uint_as_float(u);
}

__device__ __forceinline__ float warpSum(float v) {
    #pragma unroll
    for (int o = 16; o; o >>= 1) v += __shfl_xor_sync(0xffffffffu, v, o);
    return v;
}

// ---------------- RMSNorm ----------------
__global__ void rmsnorm_kernel(const float* __restrict__ x,
                               const float* __restrict__ gamma,
                               float* __restrict__ o) {
    int row = blockIdx.x;
    const float* xr = x + (size_t)row * DM_;
    float s = 0.f;
    for (int i = threadIdx.x; i < DM_; i += 256) { float v = xr[i]; s += v * v; }
    __shared__ float red[8];
    float w = warpSum(s);
    if ((threadIdx.x & 31) == 0) red[threadIdx.x >> 5] = w;
    __syncthreads();
    float tot = 0.f;
    #pragma unroll
    for (int i = 0; i < 8; i++) tot += red[i];
    float inv = rsqrtf(tot / (float)DM_ + 1e-5f);
    float* orow = o + (size_t)row * DM_;
    for (int i = threadIdx.x; i < DM_; i += 256) orow[i] = xr[i] * inv * gamma[i];
}

// =================== TF32 tensor-core GEMM (unchanged from R3) ===================
#define BM 128
#define BN 128
#define BK 32
#define ASTRIDE 36
#define BSTRIDE 136
#define STAGE_FLOATS (BM * ASTRIDE + BK * BSTRIDE)
#define GEMM_SMEM_BYTES (2 * STAGE_FLOATS * 4)

__device__ __forceinline__ void mma_tf32(float c[4], const uint32_t a[4], const uint32_t b[2]) {
    asm volatile(
        "mma.sync.aligned.m16n8k8.row.col.f32.tf32.tf32.f32 "
        "{%0,%1,%2,%3}, {%4,%5,%6,%7}, {%8,%9}, {%0,%1,%2,%3};"
        : "+f"(c[0]), "+f"(c[1]), "+f"(c[2]), "+f"(c[3])
        : "r"(a[0]), "r"(a[1]), "r"(a[2]), "r"(a[3]), "r"(b[0]), "r"(b[1]));
}

__global__ __launch_bounds__(256, 1)
void mma_gemm_kernel(const float* __restrict__ A, const float* __restrict__ Bg,
                     const float* __restrict__ Res, float* __restrict__ C,
                     int M, int N, int K, int addRes) {
    extern __shared__ float smem[];
    float* stage[2] = { smem, smem + STAGE_FLOATS };

    const int tid  = threadIdx.x;
    const int lane = tid & 31;
    const int warp = tid >> 5;
    const int gid  = lane >> 2;
    const int tg   = lane & 3;
    const int wm   = warp >> 1;
    const int wn   = warp & 1;

    const int bm = blockIdx.y * BM;
    const int bn = blockIdx.x * BN;

    const int arow = tid >> 3;
    const int acol = (tid & 7) * 4;
    const int brow = tid >> 5;
    const int bcol = (tid & 31) * 4;

    float acc[2][8][4];
    #pragma unroll
    for (int i = 0; i < 2; i++)
        #pragma unroll
        for (int j = 0; j < 8; j++)
            #pragma unroll
            for (int l = 0; l < 4; l++) acc[i][j][l] = 0.f;

    const int ntiles = K / BK;

    float4 ar[4], br[4];
    #pragma unroll
    for (int i = 0; i < 4; i++)
        ar[i] = *(const float4*)&A[(size_t)(bm + arow + 32 * i) * K + acol];
    #pragma unroll
    for (int i = 0; i < 4; i++)
        br[i] = *(const float4*)&Bg[(size_t)(brow + 8 * i) * N + bn + bcol];

    {
        float* As = stage[0];
        float* Bs = stage[0] + BM * ASTRIDE;
        #pragma unroll
        for (int i = 0; i < 4; i++) {
            float4 v = ar[i];
            v.x = tf32r(v.x); v.y = tf32r(v.y); v.z = tf32r(v.z); v.w = tf32r(v.w);
            *(float4*)&As[(arow + 32 * i) * ASTRIDE + acol] = v;
        }
        #pragma unroll
        for (int i = 0; i < 4; i++) {
            float4 v = br[i];
            v.x = tf32r(v.x); v.y = tf32r(v.y); v.z = tf32r(v.z); v.w = tf32r(v.w);
            *(float4*)&Bs[(brow + 8 * i) * BSTRIDE + bcol] = v;
        }
    }
    __syncthreads();

    int cur = 0;
    for (int t = 0; t < ntiles; t++) {
        if (t + 1 < ntiles) {
            int k0 = (t + 1) * BK;
            #pragma unroll
            for (int i = 0; i < 4; i++)
                ar[i] = *(const float4*)&A[(size_t)(bm + arow + 32 * i) * K + k0 + acol];
            #pragma unroll
            for (int i = 0; i < 4; i++)
                br[i] = *(const float4*)&Bg[(size_t)(k0 + brow + 8 * i) * N + bn + bcol];
        }

        const float* As = stage[cur];
        const float* Bs = stage[cur] + BM * ASTRIDE;

        #pragma unroll
        for (int ks = 0; ks < 4; ks++) {
            uint32_t af[2][4], bf[8][2];
            int col = ks * 8 + tg;
            #pragma unroll
            for (int mt = 0; mt < 2; mt++) {
                int r = wm * 32 + mt * 16 + gid;
                af[mt][0] = __float_as_uint(As[r * ASTRIDE + col]);
                af[mt][1] = __float_as_uint(As[(r + 8) * ASTRIDE + col]);
                af[mt][2] = __float_as_uint(As[r * ASTRIDE + col + 4]);
                af[mt][3] = __float_as_uint(As[(r + 8) * ASTRIDE + col + 4]);
            }
            #pragma unroll
            for (int nt = 0; nt < 8; nt++) {
                int c = wn * 64 + nt * 8 + gid;
                bf[nt][0] = __float_as_uint(Bs[(ks * 8 + tg) * BSTRIDE + c]);
                bf[nt][1] = __float_as_uint(Bs[(ks * 8 + tg + 4) * BSTRIDE + c]);
            }
            #pragma unroll
            for (int mt = 0; mt < 2; mt++)
                #pragma unroll
                for (int nt = 0; nt < 8; nt++)
                    mma_tf32(acc[mt][nt], af[mt], bf[nt]);
        }

        if (t + 1 < ntiles) {
            float* As2 = stage[cur ^ 1];
            float* Bs2 = stage[cur ^ 1] + BM * ASTRIDE;
            #pragma unroll
            for (int i = 0; i < 4; i++) {
                float4 v = ar[i];
                v.x = tf32r(v.x); v.y = tf32r(v.y); v.z = tf32r(v.z); v.w = tf32r(v.w);
                *(float4*)&As2[(arow + 32 * i) * ASTRIDE + acol] = v;
            }
            #pragma unroll
            for (int i = 0; i < 4; i++) {
                float4 v = br[i];
                v.x = tf32r(v.x); v.y = tf32r(v.y); v.z = tf32r(v.z); v.w = tf32r(v.w);
                *(float4*)&Bs2[(brow + 8 * i) * BSTRIDE + bcol] = v;
            }
            __syncthreads();
            cur ^= 1;
        }
    }

    #pragma unroll
    for (int mt = 0; mt < 2; mt++) {
        #pragma unroll
        for (int nt = 0; nt < 8; nt++) {
            int m0 = bm + wm * 32 + mt * 16 + gid;
            int n0 = bn + wn * 64 + nt * 8 + tg * 2;
            float2 v0 = make_float2(acc[mt][nt][0], acc[mt][nt][1]);
            float2 v1 = make_float2(acc[mt][nt][2], acc[mt][nt][3]);
            if (addRes) {
                float2 r0 = *(const float2*)&Res[(size_t)m0 * N + n0];
                float2 r1 = *(const float2*)&Res[(size_t)(m0 + 8) * N + n0];
                v0.x += r0.x; v0.y += r0.y;
                v1.x += r1.x; v1.y += r1.y;
            }
            *(float2*)&C[(size_t)m0 * N + n0] = v0;
            *(float2*)&C[(size_t)(m0 + 8) * N + n0] = v1;
        }
    }
}

// ---------------- RoPE ----------------
__global__ void rope_kernel(float* __restrict__ qkv) {
    int idx = blockIdx.x * blockDim.x + threadIdx.x;
    const int total = B_ * S_ * 2 * H_ * (DH_ / 2);
    if (idx >= total) return;
    int d = idx & 31; idx >>= 5;
    int h = idx % H_; idx /= H_;
    int e = idx & 1;  idx >>= 1;
    int s = idx % S_;
    int b = idx / S_;
    float w = (float)(2 * d) / (float)DH_;
    float inv_freq = 1.0f / powf(10000.0f, w);
    float ang = (float)s * inv_freq;
    float cs = cosf(ang);
    float sn = sinf(ang);
    size_t base = (size_t)(b * S_ + s) * DQKV + e * DM_ + h * DH_;
    float x1 = qkv[base + d];
    float x2 = qkv[base + d + 32];
    qkv[base + d]      = x1 * cs - x2 * sn;
    qkv[base + d + 32] = x2 * cs + x1 * sn;
}

// =================== tiled sliding-window attention ===================
// Block = (b, h, 64-query tile). Keys window: 192 rows [qt0-64, qt0+127].
#define QT 64
#define KT 192
#define SSTR 193    // scores row stride (odd: 4*193 % 32 == 4 -> <=2-way on PV p loads)
#define ATTN_Q_FLOATS   (QT * DH_)          // 4096
#define ATTN_K_FLOATS   (KT * DH_)          // 12288
#define ATTN_S_FLOATS   (QT * SSTR)         // 12352
#define ATTN_SMEM_FLOATS (ATTN_Q_FLOATS + 2 * ATTN_K_FLOATS + ATTN_S_FLOATS)
#define ATTN_SMEM_BYTES  (ATTN_SMEM_FLOATS * 4)   // 164096

// swizzled float4-chunk offset inside a 64-float row: chunk' = chunk ^ ((row>>2)&15)
__device__ __forceinline__ int ksw(int row, int chunk) {
    return row * DH_ + 4 * (chunk ^ ((row >> 2) & 15));
}

__global__ __launch_bounds__(256, 1)
void attn_tile_kernel(const float* __restrict__ qkv, const int* __restrict__ pmask,
                      float* __restrict__ out) {
    extern __shared__ float sm[];
    float* Qs = sm;                         // [QT][64]
    float* Ks = Qs + ATTN_Q_FLOATS;         // [KT][64] swizzled
    float* Vs = Ks + ATTN_K_FLOATS;         // [KT][64] plain
    float* Sc = Vs + ATTN_K_FLOATS;         // [QT][SSTR]

    const int qt0 = blockIdx.x * QT;
    const int h   = blockIdx.y;
    const int b   = blockIdx.z;
    const int tid = threadIdx.x;

    // ---- load Q (always in range) ----
    for (int i = tid; i < QT * 16; i += 256) {
        int r = i >> 4, c4 = (i & 15) * 4;
        float4 v = *(const float4*)&qkv[(size_t)(b * S_ + qt0 + r) * DQKV + h * DH_ + c4];
        v.x = tf32r(v.x); v.y = tf32r(v.y); v.z = tf32r(v.z); v.w = tf32r(v.w);
        *(float4*)&Qs[r * DH_ + c4] = v;
    }
    // ---- load K (swizzled) and V (plain); out-of-range rows -> 0 ----
    for (int i = tid; i < KT * 16; i += 256) {
        int r = i >> 4, c = i & 15;
        int j = qt0 - WIN + r;
        float4 kv = make_float4(0.f, 0.f, 0.f, 0.f), vv = kv;
        if (j >= 0 && j < S_) {
            size_t base = (size_t)(b * S_ + j) * DQKV + h * DH_ + c * 4;
            kv = *(const float4*)&qkv[base + DM_];
            vv = *(const float4*)&qkv[base + 2 * DM_];
            kv.x = tf32r(kv.x); kv.y = tf32r(kv.y); kv.z = tf32r(kv.z); kv.w = tf32r(kv.w);
            vv.x = tf32r(vv.x); vv.y = tf32r(vv.y); vv.z = tf32r(vv.z); vv.w = tf32r(vv.w);
        }
        *(float4*)&Ks[ksw(r, c)] = kv;
        *(float4*)&Vs[r * DH_ + c * 4] = vv;
    }
    __syncthreads();

    // ---- QK^T: thread (tk = tid&15, tq = tid>>4) computes 4q x 4k per chunk ----
    {
        const int tk = tid & 15;      // distinct across half-warp -> swizzled K rows
        const int tq = tid >> 4;      // 0..15
        #pragma unroll
        for (int kp = 0; kp < 3; kp++) {
            const int kbase = kp * 64 + tk * 4;
            float acc[4][4];
            #pragma unroll
            for (int i = 0; i < 4; i++)
                #pragma unroll
                for (int u = 0; u < 4; u++) acc[i][u] = 0.f;

            for (int c = 0; c < 16; c++) {
                float4 qv[4], kv[4];
                #pragma unroll
                for (int i = 0; i < 4; i++)
                    qv[i] = *(const float4*)&Qs[(tq * 4 + i) * DH_ + c * 4];
                #pragma unroll
                for (int u = 0; u < 4; u++)
                    kv[u] = *(const float4*)&Ks[ksw(kbase + u, c)];
                #pragma unroll
                for (int i = 0; i < 4; i++)
                    #pragma unroll
                    for (int u = 0; u < 4; u++)
                        acc[i][u] += qv[i].x * kv[u].x + qv[i].y * kv[u].y
                                   + qv[i].z * kv[u].z + qv[i].w * kv[u].w;
            }
            #pragma unroll
            for (int i = 0; i < 4; i++) {
                int ql = tq * 4 + i;
                int qg = qt0 + ql;
                #pragma unroll
                for (int u = 0; u < 4; u++) {
                    int kr = kbase + u;
                    int j = qt0 - WIN + kr;
                    float s;
                    if (j < 0 || j >= S_) {
                        s = -1e30f;          // key does not exist -> exact 0 after exp
                    } else {
                        s = acc[i][u] * 0.125f;
                        int diff = j - qg;
                        if (diff > WIN || diff < -WIN) s -= 10000.0f;
                        if (pmask[b * S_ + j] == 0)    s -= 10000.0f;
                    }
                    Sc[ql * SSTR + kr] = s;
                }
            }
        }
    }
    __syncthreads();

    // ---- softmax per row (4 threads / row, shfl within quad) ----
    {
        const int row = tid >> 2, sub = tid & 3;
        float m = -1e30f;
        for (int k = sub; k < KT; k += 4) m = fmaxf(m, Sc[row * SSTR + k]);
        m = fmaxf(m, __shfl_xor_sync(0xffffffffu, m, 1));
        m = fmaxf(m, __shfl_xor_sync(0xffffffffu, m, 2));
        float ssum = 0.f;
        for (int k = sub; k < KT; k += 4) {
            float e = expf(Sc[row * SSTR + k] - m);
            Sc[row * SSTR + k] = e;
            ssum += e;
        }
        ssum += __shfl_xor_sync(0xffffffffu, ssum, 1);
        ssum += __shfl_xor_sync(0xffffffffu, ssum, 2);
        for (int k = sub; k < KT; k += 4)
            Sc[row * SSTR + k] = tf32r(Sc[row * SSTR + k] / ssum);
    }
    __syncthreads();

    // ---- PV: thread (tq = tid&15 -> 4 q rows, td = tid>>4 -> 4 dh cols) ----
    {
        const int q4 = (tid & 15) * 4;
        const int d4 = (tid >> 4) * 4;
        float o[4][4];
        #pragma unroll
        for (int i = 0; i < 4; i++)
            #pragma unroll
            for (int u = 0; u < 4; u++) o[i][u] = 0.f;

        for (int k = 0; k < KT; k++) {
            float4 vv = *(const float4*)&Vs[k * DH_ + d4];
            #pragma unroll
            for (int i = 0; i < 4; i++) {
                float p = Sc[(q4 + i) * SSTR + k];
                o[i][0] += p * vv.x;
                o[i][1] += p * vv.y;
                o[i][2] += p * vv.z;
                o[i][3] += p * vv.w;
            }
        }
        #pragma unroll
        for (int i = 0; i < 4; i++) {
            float4 v = make_float4(o[i][0], o[i][1], o[i][2], o[i][3]);
            *(float4*)&out[(size_t)(b * S_ + qt0 + q4 + i) * DM_ + h * DH_ + d4] = v;
        }
    }
}

// ---------------- gelu(gate) * up ----------------
__global__ void gelumul_kernel(float* __restrict__ g, const float* __restrict__ u, int n) {
    int i = blockIdx.x * blockDim.x + threadIdx.x;
    if (i >= n) return;
    float x = g[i];
    float t = tanhf(0.7978845608028654f * (x + 0.044715f * x * x * x));
    g[i] = 0.5f * x * (1.0f + t) * u[i];
}

// ---------------- launch ----------------
extern "C" void kernel_launch(void* const* d_in, const int* in_sizes, int n_in,
                              void* d_out, int out_size) {
    const float* x          = (const float*)d_in[0];
    const int*   pmask      = (const int*)  d_in[1];
    const float* w_qkv      = (const float*)d_in[2];
    const float* w_o        = (const float*)d_in[3];
    const float* gamma_attn = (const float*)d_in[4];
    const float* gamma_mlp  = (const float*)d_in[5];
    const float* w_i0       = (const float*)d_in[6];
    const float* w_i1       = (const float*)d_in[7];
    const float* w_mo       = (const float*)d_in[8];
    float* out = (float*)d_out;

    float *h, *qkv, *attn, *x1, *gate, *up;
    cudaGetSymbolAddress((void**)&h,    g_h);
    cudaGetSymbolAddress((void**)&qkv,  g_qkv);
    cudaGetSymbolAddress((void**)&attn, g_attn);
    cudaGetSymbolAddress((void**)&x1,   g_x1);
    cudaGetSymbolAddress((void**)&gate, g_gate);
    cudaGetSymbolAddress((void**)&up,   g_up);

    cudaFuncSetAttribute(mma_gemm_kernel,
                         cudaFuncAttributeMaxDynamicSharedMemorySize, GEMM_SMEM_BYTES);
    cudaFuncSetAttribute(attn_tile_kernel,
                         cudaFuncAttributeMaxDynamicSharedMemorySize, ATTN_SMEM_BYTES);

    rmsnorm_kernel<<<ROWS, 256>>>(x, gamma_attn, h);
    mma_gemm_kernel<<<dim3(DQKV / BN, ROWS / BM), 256, GEMM_SMEM_BYTES>>>(
        h, w_qkv, nullptr, qkv, ROWS, DQKV, DM_, 0);
    {
        int total = B_ * S_ * 2 * H_ * (DH_ / 2);
        rope_kernel<<<(total + 255) / 256, 256>>>(qkv);
    }
    attn_tile_kernel<<<dim3(S_ / QT, H_, B_), 256, ATTN_SMEM_BYTES>>>(qkv, pmask, attn);
    mma_gemm_kernel<<<dim3(DM_ / BN, ROWS / BM), 256, GEMM_SMEM_BYTES>>>(
        attn, w_o, x, x1, ROWS, DM_, DM_, 1);
    rmsnorm_kernel<<<ROWS, 256>>>(x1, gamma_mlp, h);
    mma_gemm_kernel<<<dim3(DI_ / BN, ROWS / BM), 256, GEMM_SMEM_BYTES>>>(
        h, w_i0, nullptr, gate, ROWS, DI_, DM_, 0);
    mma_gemm_kernel<<<dim3(DI_ / BN, ROWS / BM), 256, GEMM_SMEM_BYTES>>>(
        h, w_i1, nullptr, up, ROWS, DI_, DM_, 0);
    {
        int n = ROWS * DI_;
        gelumul_kernel<<<(n + 255) / 256, 256>>>(gate, up, n);
    }
    mma_gemm_kernel<<<dim3(DM_ / BN, ROWS / BM), 256, GEMM_SMEM_BYTES>>>(
        gate, w_mo, x1, out, ROWS, DM_, DI_, 1);
}

// round 5
// speedup vs baseline: 2.9930x; 1.2306x over previous
#include <cuda_runtime.h>
#include <cuda_bf16.h>
#include <math.h>
#include <stdint.h>

// ---------------- problem constants ----------------
#define B_   2
#define S_   4096
#define DM_  768
#define DI_  1152
#define H_   12
#define DH_  64
#define ROWS (B_ * S_)          // 8192
#define DQKV (3 * DM_)          // 2304
#define WIN  64                 // WINDOW/2

// ---------------- scratch ----------------
__device__ float g_h[ROWS * DM_];
__device__ float g_qkv[ROWS * DQKV];
__device__ float g_attn[ROWS * DM_];
__device__ float g_x1[ROWS * DM_];
__device__ float g_gate[ROWS * DI_];
__device__ float g_up[ROWS * DI_];
// tf32-rounded weight copies
__device__ float g_wqkv[DM_ * DQKV];
__device__ float g_wo  [DM_ * DM_];
__device__ float g_wi0 [DM_ * DI_];
__device__ float g_wi1 [DM_ * DI_];
__device__ float g_wmo [DI_ * DM_];

// ---------------- TF32 rounding ----------------
__device__ __forceinline__ float tf32r(float x) {
    uint32_t u;
    asm("cvt.rna.tf32.f32 %0, %1;" : "=r"(u) : "f"(x));
    return __uint_as_float(u);
}

__device__ __forceinline__ float warpSum(float v) {
    #pragma unroll
    for (int o = 16; o; o >>= 1) v += __shfl_xor_sync(0xffffffffu, v, o);
    return v;
}

// ---------------- weight pre-rounding ----------------
__global__ void tf32cvt_kernel(const float* __restrict__ in, float* __restrict__ out, int n) {
    int i = blockIdx.x * blockDim.x + threadIdx.x;
    if (i < n) out[i] = tf32r(in[i]);
}

// ---------------- RMSNorm (emits tf32-rounded output: it only feeds GEMM-A) ----
__global__ void rmsnorm_kernel(const float* __restrict__ x,
                               const float* __restrict__ gamma,
                               float* __restrict__ o) {
    int row = blockIdx.x;
    const float* xr = x + (size_t)row * DM_;
    float s = 0.f;
    for (int i = threadIdx.x; i < DM_; i += 256) { float v = xr[i]; s += v * v; }
    __shared__ float red[8];
    float w = warpSum(s);
    if ((threadIdx.x & 31) == 0) red[threadIdx.x >> 5] = w;
    __syncthreads();
    float tot = 0.f;
    #pragma unroll
    for (int i = 0; i < 8; i++) tot += red[i];
    float inv = rsqrtf(tot / (float)DM_ + 1e-5f);
    float* orow = o + (size_t)row * DM_;
    for (int i = threadIdx.x; i < DM_; i += 256) orow[i] = tf32r(xr[i] * inv * gamma[i]);
}

// =================== TF32 tensor-core GEMM, cp.async, 2 CTA/SM ===================
// Operands in gmem are ALREADY tf32-valued fp32. No cvt in kernel.
#define BM 128
#define BN 128
#define BK 32
#define ASTRIDE 36
#define BSTRIDE 136
#define STAGE_FLOATS (BM * ASTRIDE + BK * BSTRIDE)   // 8960
#define GEMM_SMEM_BYTES (2 * STAGE_FLOATS * 4)        // 71680

__device__ __forceinline__ void mma_tf32(float c[4], const uint32_t a[4], const uint32_t b[2]) {
    asm volatile(
        "mma.sync.aligned.m16n8k8.row.col.f32.tf32.tf32.f32 "
        "{%0,%1,%2,%3}, {%4,%5,%6,%7}, {%8,%9}, {%0,%1,%2,%3};"
        : "+f"(c[0]), "+f"(c[1]), "+f"(c[2]), "+f"(c[3])
        : "r"(a[0]), "r"(a[1]), "r"(a[2]), "r"(a[3]), "r"(b[0]), "r"(b[1]));
}

__device__ __forceinline__ void cp16(float* dst_smem, const float* src) {
    uint32_t d = (uint32_t)__cvta_generic_to_shared(dst_smem);
    asm volatile("cp.async.cg.shared.global [%0], [%1], 16;" :: "r"(d), "l"(src));
}

__global__ __launch_bounds__(256, 2)
void mma_gemm_kernel(const float* __restrict__ A, const float* __restrict__ Bg,
                     const float* __restrict__ Res, float* __restrict__ C,
                     int M, int N, int K, int addRes) {
    extern __shared__ float smem[];
    float* stage[2] = { smem, smem + STAGE_FLOATS };

    const int tid  = threadIdx.x;
    const int lane = tid & 31;
    const int warp = tid >> 5;
    const int gid  = lane >> 2;
    const int tg   = lane & 3;
    const int wm   = warp >> 1;
    const int wn   = warp & 1;

    const int bm = blockIdx.y * BM;
    const int bn = blockIdx.x * BN;

    const int arow = tid >> 3;         // 0..31
    const int acol = (tid & 7) * 4;    // 0..28
    const int brow = tid >> 5;         // 0..7
    const int bcol = (tid & 31) * 4;   // 0..124

    float acc[2][8][4];
    #pragma unroll
    for (int i = 0; i < 2; i++)
        #pragma unroll
        for (int j = 0; j < 8; j++)
            #pragma unroll
            for (int l = 0; l < 4; l++) acc[i][j][l] = 0.f;

    const int ntiles = K / BK;

    // issue tile t into buffer buf
    #define ISSUE_TILE(t, buf) do {                                            \
        float* As_ = stage[buf];                                               \
        float* Bs_ = stage[buf] + BM * ASTRIDE;                                \
        int k0_ = (t) * BK;                                                    \
        _Pragma("unroll")                                                      \
        for (int i = 0; i < 4; i++)                                            \
            cp16(&As_[(arow + 32 * i) * ASTRIDE + acol],                       \
                 &A[(size_t)(bm + arow + 32 * i) * K + k0_ + acol]);           \
        _Pragma("unroll")                                                      \
        for (int i = 0; i < 4; i++)                                            \
            cp16(&Bs_[(brow + 8 * i) * BSTRIDE + bcol],                        \
                 &Bg[(size_t)(k0_ + brow + 8 * i) * N + bn + bcol]);           \
        asm volatile("cp.async.commit_group;");                                \
    } while (0)

    ISSUE_TILE(0, 0);

    for (int t = 0; t < ntiles; t++) {
        if (t + 1 < ntiles) {
            ISSUE_TILE(t + 1, (t + 1) & 1);
            asm volatile("cp.async.wait_group 1;");
        } else {
            asm volatile("cp.async.wait_group 0;");
        }
        __syncthreads();

        const float* As = stage[t & 1];
        const float* Bs = stage[t & 1] + BM * ASTRIDE;

        #pragma unroll
        for (int ks = 0; ks < 4; ks++) {
            uint32_t af[2][4], bf[8][2];
            int col = ks * 8 + tg;
            #pragma unroll
            for (int mt = 0; mt < 2; mt++) {
                int r = wm * 32 + mt * 16 + gid;
                af[mt][0] = __float_as_uint(As[r * ASTRIDE + col]);
                af[mt][1] = __float_as_uint(As[(r + 8) * ASTRIDE + col]);
                af[mt][2] = __float_as_uint(As[r * ASTRIDE + col + 4]);
                af[mt][3] = __float_as_uint(As[(r + 8) * ASTRIDE + col + 4]);
            }
            #pragma unroll
            for (int nt = 0; nt < 8; nt++) {
                int c = wn * 64 + nt * 8 + gid;
                bf[nt][0] = __float_as_uint(Bs[(ks * 8 + tg) * BSTRIDE + c]);
                bf[nt][1] = __float_as_uint(Bs[(ks * 8 + tg + 4) * BSTRIDE + c]);
            }
            #pragma unroll
            for (int mt = 0; mt < 2; mt++)
                #pragma unroll
                for (int nt = 0; nt < 8; nt++)
                    mma_tf32(acc[mt][nt], af[mt], bf[nt]);
        }
        __syncthreads();
    }

    #pragma unroll
    for (int mt = 0; mt < 2; mt++) {
        #pragma unroll
        for (int nt = 0; nt < 8; nt++) {
            int m0 = bm + wm * 32 + mt * 16 + gid;
            int n0 = bn + wn * 64 + nt * 8 + tg * 2;
            float2 v0 = make_float2(acc[mt][nt][0], acc[mt][nt][1]);
            float2 v1 = make_float2(acc[mt][nt][2], acc[mt][nt][3]);
            if (addRes) {
                float2 r0 = *(const float2*)&Res[(size_t)m0 * N + n0];
                float2 r1 = *(const float2*)&Res[(size_t)(m0 + 8) * N + n0];
                v0.x += r0.x; v0.y += r0.y;
                v1.x += r1.x; v1.y += r1.y;
            }
            *(float2*)&C[(size_t)m0 * N + n0] = v0;
            *(float2*)&C[(size_t)(m0 + 8) * N + n0] = v1;
        }
    }
}

// ---------------- RoPE ----------------
__global__ void rope_kernel(float* __restrict__ qkv) {
    int idx = blockIdx.x * blockDim.x + threadIdx.x;
    const int total = B_ * S_ * 2 * H_ * (DH_ / 2);
    if (idx >= total) return;
    int d = idx & 31; idx >>= 5;
    int h = idx % H_; idx /= H_;
    int e = idx & 1;  idx >>= 1;
    int s = idx % S_;
    int b = idx / S_;
    float w = (float)(2 * d) / (float)DH_;
    float inv_freq = 1.0f / powf(10000.0f, w);
    float ang = (float)s * inv_freq;
    float cs = cosf(ang);
    float sn = sinf(ang);
    size_t base = (size_t)(b * S_ + s) * DQKV + e * DM_ + h * DH_;
    float x1 = qkv[base + d];
    float x2 = qkv[base + d + 32];
    qkv[base + d]      = x1 * cs - x2 * sn;
    qkv[base + d + 32] = x2 * cs + x1 * sn;
}

// =================== tiled sliding-window attention ===================
#define QT 64
#define KT 192
#define SSTR 196    // scores row stride (multiple of 4 for float4 PV loads)
#define ATTN_Q_FLOATS   (QT * DH_)
#define ATTN_K_FLOATS   (KT * DH_)
#define ATTN_S_FLOATS   (QT * SSTR)
#define ATTN_SMEM_FLOATS (ATTN_Q_FLOATS + 2 * ATTN_K_FLOATS + ATTN_S_FLOATS)
#define ATTN_SMEM_BYTES  (ATTN_SMEM_FLOATS * 4)

__device__ __forceinline__ int ksw(int row, int chunk) {
    return row * DH_ + 4 * (chunk ^ ((row >> 2) & 15));
}

__global__ __launch_bounds__(256, 1)
void attn_tile_kernel(const float* __restrict__ qkv, const int* __restrict__ pmask,
                      float* __restrict__ out) {
    extern __shared__ float sm[];
    float* Qs = sm;
    float* Ks = Qs + ATTN_Q_FLOATS;
    float* Vs = Ks + ATTN_K_FLOATS;
    float* Sc = Vs + ATTN_K_FLOATS;

    const int qt0 = blockIdx.x * QT;
    const int h   = blockIdx.y;
    const int b   = blockIdx.z;
    const int tid = threadIdx.x;

    for (int i = tid; i < QT * 16; i += 256) {
        int r = i >> 4, c4 = (i & 15) * 4;
        float4 v = *(const float4*)&qkv[(size_t)(b * S_ + qt0 + r) * DQKV + h * DH_ + c4];
        v.x = tf32r(v.x); v.y = tf32r(v.y); v.z = tf32r(v.z); v.w = tf32r(v.w);
        *(float4*)&Qs[r * DH_ + c4] = v;
    }
    for (int i = tid; i < KT * 16; i += 256) {
        int r = i >> 4, c = i & 15;
        int j = qt0 - WIN + r;
        float4 kv = make_float4(0.f, 0.f, 0.f, 0.f), vv = kv;
        if (j >= 0 && j < S_) {
            size_t base = (size_t)(b * S_ + j) * DQKV + h * DH_ + c * 4;
            kv = *(const float4*)&qkv[base + DM_];
            vv = *(const float4*)&qkv[base + 2 * DM_];
            kv.x = tf32r(kv.x); kv.y = tf32r(kv.y); kv.z = tf32r(kv.z); kv.w = tf32r(kv.w);
            vv.x = tf32r(vv.x); vv.y = tf32r(vv.y); vv.z = tf32r(vv.z); vv.w = tf32r(vv.w);
        }
        *(float4*)&Ks[ksw(r, c)] = kv;
        *(float4*)&Vs[r * DH_ + c * 4] = vv;
    }
    __syncthreads();

    {
        const int tk = tid & 15;
        const int tq = tid >> 4;
        #pragma unroll
        for (int kp = 0; kp < 3; kp++) {
            const int kbase = kp * 64 + tk * 4;
            float acc[4][4];
            #pragma unroll
            for (int i = 0; i < 4; i++)
                #pragma unroll
                for (int u = 0; u < 4; u++) acc[i][u] = 0.f;

            for (int c = 0; c < 16; c++) {
                float4 qv[4], kv[4];
                #pragma unroll
                for (int i = 0; i < 4; i++)
                    qv[i] = *(const float4*)&Qs[(tq * 4 + i) * DH_ + c * 4];
                #pragma unroll
                for (int u = 0; u < 4; u++)
                    kv[u] = *(const float4*)&Ks[ksw(kbase + u, c)];
                #pragma unroll
                for (int i = 0; i < 4; i++)
                    #pragma unroll
                    for (int u = 0; u < 4; u++)
                        acc[i][u] += qv[i].x * kv[u].x + qv[i].y * kv[u].y
                                   + qv[i].z * kv[u].z + qv[i].w * kv[u].w;
            }
            #pragma unroll
            for (int i = 0; i < 4; i++) {
                int ql = tq * 4 + i;
                int qg = qt0 + ql;
                #pragma unroll
                for (int u = 0; u < 4; u++) {
                    int kr = kbase + u;
                    int j = qt0 - WIN + kr;
                    float s;
                    if (j < 0 || j >= S_) {
                        s = -1e30f;
                    } else {
                        s = acc[i][u] * 0.125f;
                        int diff = j - qg;
                        if (diff > WIN || diff < -WIN) s -= 10000.0f;
                        if (pmask[b * S_ + j] == 0)    s -= 10000.0f;
                    }
                    Sc[ql * SSTR + kr] = s;
                }
            }
        }
    }
    __syncthreads();

    {
        const int row = tid >> 2, sub = tid & 3;
        float m = -1e30f;
        for (int k = sub; k < KT; k += 4) m = fmaxf(m, Sc[row * SSTR + k]);
        m = fmaxf(m, __shfl_xor_sync(0xffffffffu, m, 1));
        m = fmaxf(m, __shfl_xor_sync(0xffffffffu, m, 2));
        float ssum = 0.f;
        for (int k = sub; k < KT; k += 4) {
            float e = expf(Sc[row * SSTR + k] - m);
            Sc[row * SSTR + k] = e;
            ssum += e;
        }
        ssum += __shfl_xor_sync(0xffffffffu, ssum, 1);
        ssum += __shfl_xor_sync(0xffffffffu, ssum, 2);
        for (int k = sub; k < KT; k += 4)
            Sc[row * SSTR + k] = tf32r(Sc[row * SSTR + k] / ssum);
    }
    __syncthreads();

    {
        const int q4 = (tid & 15) * 4;
        const int d4 = (tid >> 4) * 4;
        float o[4][4];
        #pragma unroll
        for (int i = 0; i < 4; i++)
            #pragma unroll
            for (int u = 0; u < 4; u++) o[i][u] = 0.f;

        for (int k = 0; k < KT; k += 4) {
            float4 pv[4];
            #pragma unroll
            for (int i = 0; i < 4; i++)
                pv[i] = *(const float4*)&Sc[(q4 + i) * SSTR + k];
            #pragma unroll
            for (int kk = 0; kk < 4; kk++) {
                float4 vv = *(const float4*)&Vs[(k + kk) * DH_ + d4];
                #pragma unroll
                for (int i = 0; i < 4; i++) {
                    float p = (kk == 0) ? pv[i].x : (kk == 1) ? pv[i].y : (kk == 2) ? pv[i].z : pv[i].w;
                    o[i][0] += p * vv.x;
                    o[i][1] += p * vv.y;
                    o[i][2] += p * vv.z;
                    o[i][3] += p * vv.w;
                }
            }
        }
        #pragma unroll
        for (int i = 0; i < 4; i++) {
            // output feeds GEMM-A (attn @ w_o): round here (matches reference TF32 einsum input)
            float4 v = make_float4(tf32r(o[i][0]), tf32r(o[i][1]), tf32r(o[i][2]), tf32r(o[i][3]));
            *(float4*)&out[(size_t)(b * S_ + qt0 + q4 + i) * DM_ + h * DH_ + d4] = v;
        }
    }
}

// ---------------- gelu(gate) * up (emits tf32-rounded: only feeds GEMM-A) ----
__global__ void gelumul_kernel(float* __restrict__ g, const float* __restrict__ u, int n) {
    int i = blockIdx.x * blockDim.x + threadIdx.x;
    if (i >= n) return;
    float x = g[i];
    float t = tanhf(0.7978845608028654f * (x + 0.044715f * x * x * x));
    g[i] = tf32r(0.5f * x * (1.0f + t) * u[i]);
}

// ---------------- launch ----------------
extern "C" void kernel_launch(void* const* d_in, const int* in_sizes, int n_in,
                              void* d_out, int out_size) {
    const float* x          = (const float*)d_in[0];
    const int*   pmask      = (const int*)  d_in[1];
    const float* w_qkv      = (const float*)d_in[2];
    const float* w_o        = (const float*)d_in[3];
    const float* gamma_attn = (const float*)d_in[4];
    const float* gamma_mlp  = (const float*)d_in[5];
    const float* w_i0       = (const float*)d_in[6];
    const float* w_i1       = (const float*)d_in[7];
    const float* w_mo       = (const float*)d_in[8];
    float* out = (float*)d_out;

    float *h, *qkv, *attn, *x1, *gate, *up;
    float *wqkv, *wo, *wi0, *wi1, *wmo;
    cudaGetSymbolAddress((void**)&h,    g_h);
    cudaGetSymbolAddress((void**)&qkv,  g_qkv);
    cudaGetSymbolAddress((void**)&attn, g_attn);
    cudaGetSymbolAddress((void**)&x1,   g_x1);
    cudaGetSymbolAddress((void**)&gate, g_gate);
    cudaGetSymbolAddress((void**)&up,   g_up);
    cudaGetSymbolAddress((void**)&wqkv, g_wqkv);
    cudaGetSymbolAddress((void**)&wo,   g_wo);
    cudaGetSymbolAddress((void**)&wi0,  g_wi0);
    cudaGetSymbolAddress((void**)&wi1,  g_wi1);
    cudaGetSymbolAddress((void**)&wmo,  g_wmo);

    cudaFuncSetAttribute(mma_gemm_kernel,
                         cudaFuncAttributeMaxDynamicSharedMemorySize, GEMM_SMEM_BYTES);
    cudaFuncSetAttribute(attn_tile_kernel,
                         cudaFuncAttributeMaxDynamicSharedMemorySize, ATTN_SMEM_BYTES);

    // pre-round weights to tf32 (once per launch; deterministic)
    tf32cvt_kernel<<<(DM_ * DQKV + 255) / 256, 256>>>(w_qkv, wqkv, DM_ * DQKV);
    tf32cvt_kernel<<<(DM_ * DM_  + 255) / 256, 256>>>(w_o,   wo,   DM_ * DM_);
    tf32cvt_kernel<<<(DM_ * DI_  + 255) / 256, 256>>>(w_i0,  wi0,  DM_ * DI_);
    tf32cvt_kernel<<<(DM_ * DI_  + 255) / 256, 256>>>(w_i1,  wi1,  DM_ * DI_);
    tf32cvt_kernel<<<(DI_ * DM_  + 255) / 256, 256>>>(w_mo,  wmo,  DI_ * DM_);

    rmsnorm_kernel<<<ROWS, 256>>>(x, gamma_attn, h);
    mma_gemm_kernel<<<dim3(DQKV / BN, ROWS / BM), 256, GEMM_SMEM_BYTES>>>(
        h, wqkv, nullptr, qkv, ROWS, DQKV, DM_, 0);
    {
        int total = B_ * S_ * 2 * H_ * (DH_ / 2);
        rope_kernel<<<(total + 255) / 256, 256>>>(qkv);
    }
    attn_tile_kernel<<<dim3(S_ / QT, H_, B_), 256, ATTN_SMEM_BYTES>>>(qkv, pmask, attn);
    mma_gemm_kernel<<<dim3(DM_ / BN, ROWS / BM), 256, GEMM_SMEM_BYTES>>>(
        attn, wo, x, x1, ROWS, DM_, DM_, 1);
    rmsnorm_kernel<<<ROWS, 256>>>(x1, gamma_mlp, h);
    mma_gemm_kernel<<<dim3(DI_ / BN, ROWS / BM), 256, GEMM_SMEM_BYTES>>>(
        h, wi0, nullptr, gate, ROWS, DI_, DM_, 0);
    mma_gemm_kernel<<<dim3(DI_ / BN, ROWS / BM), 256, GEMM_SMEM_BYTES>>>(
        h, wi1, nullptr, up, ROWS, DI_, DM_, 0);
    {
        int n = ROWS * DI_;
        gelumul_kernel<<<(n + 255) / 256, 256>>>(gate, up, n);
    }
    mma_gemm_kernel<<<dim3(DM_ / BN, ROWS / BM), 256, GEMM_SMEM_BYTES>>>(
        gate, wmo, x1, out, ROWS, DM_, DI_, 1);
}

// round 6
// speedup vs baseline: 3.4540x; 1.1540x over previous
#include <cuda_runtime.h>
#include <cuda_bf16.h>
#include <math.h>
#include <stdint.h>

// ---------------- problem constants ----------------
#define B_   2
#define S_   4096
#define DM_  768
#define DI_  1152
#define H_   12
#define DH_  64
#define ROWS (B_ * S_)          // 8192
#define DQKV (3 * DM_)          // 2304
#define WIN  64                 // WINDOW/2

// ---------------- scratch ----------------
__device__ float g_h[ROWS * DM_];
__device__ float g_qkv[ROWS * DQKV];
__device__ float g_attn[ROWS * DM_];
__device__ float g_x1[ROWS * DM_];
__device__ float g_gate[ROWS * DI_];
__device__ float g_act[ROWS * DI_];
// tf32-rounded weights
__device__ float g_wqkv[DM_ * DQKV];
__device__ float g_wo  [DM_ * DM_];
__device__ float g_wi0 [DM_ * DI_];
__device__ float g_wi1 [DM_ * DI_];
__device__ float g_wmo [DI_ * DM_];

// ---------------- TF32 rounding ----------------
__device__ __forceinline__ float tf32r(float x) {
    uint32_t u;
    asm("cvt.rna.tf32.f32 %0, %1;" : "=r"(u) : "f"(x));
    return __uint_as_float(u);
}

__device__ __forceinline__ float warpSum(float v) {
    #pragma unroll
    for (int o = 16; o; o >>= 1) v += __shfl_xor_sync(0xffffffffu, v, o);
    return v;
}

// ---------------- weight pre-rounding (float4) ----------------
__global__ void tf32cvt4_kernel(const float4* __restrict__ in, float4* __restrict__ out, int n4) {
    int i = blockIdx.x * blockDim.x + threadIdx.x;
    if (i >= n4) return;
    float4 v = in[i];
    v.x = tf32r(v.x); v.y = tf32r(v.y); v.z = tf32r(v.z); v.w = tf32r(v.w);
    out[i] = v;
}

// ---------------- RMSNorm (tf32-rounded output; feeds GEMM-A only) ----------
__global__ void rmsnorm_kernel(const float* __restrict__ x,
                               const float* __restrict__ gamma,
                               float* __restrict__ o) {
    int row = blockIdx.x;
    const float* xr = x + (size_t)row * DM_;
    float s = 0.f;
    for (int i = threadIdx.x; i < DM_; i += 256) { float v = xr[i]; s += v * v; }
    __shared__ float red[8];
    float w = warpSum(s);
    if ((threadIdx.x & 31) == 0) red[threadIdx.x >> 5] = w;
    __syncthreads();
    float tot = 0.f;
    #pragma unroll
    for (int i = 0; i < 8; i++) tot += red[i];
    float inv = rsqrtf(tot / (float)DM_ + 1e-5f);
    float* orow = o + (size_t)row * DM_;
    for (int i = threadIdx.x; i < DM_; i += 256) orow[i] = tf32r(xr[i] * inv * gamma[i]);
}

// =================== TF32 tensor-core GEMM (cp.async, 2 CTA/SM) ===================
// mode 0: C = acc ; mode 1: C = Res + acc ; mode 2: C = tf32r(gelu(Res) * acc)
#define BM 128
#define BN 128
#define BK 32
#define ASTRIDE 36
#define BSTRIDE 136
#define STAGE_FLOATS (BM * ASTRIDE + BK * BSTRIDE)
#define GEMM_SMEM_BYTES (2 * STAGE_FLOATS * 4)

__device__ __forceinline__ void mma_tf32(float c[4], const uint32_t a[4], const uint32_t b[2]) {
    asm volatile(
        "mma.sync.aligned.m16n8k8.row.col.f32.tf32.tf32.f32 "
        "{%0,%1,%2,%3}, {%4,%5,%6,%7}, {%8,%9}, {%0,%1,%2,%3};"
        : "+f"(c[0]), "+f"(c[1]), "+f"(c[2]), "+f"(c[3])
        : "r"(a[0]), "r"(a[1]), "r"(a[2]), "r"(a[3]), "r"(b[0]), "r"(b[1]));
}

__device__ __forceinline__ void cp16(float* dst_smem, const float* src) {
    uint32_t d = (uint32_t)__cvta_generic_to_shared(dst_smem);
    asm volatile("cp.async.cg.shared.global [%0], [%1], 16;" :: "r"(d), "l"(src));
}

__device__ __forceinline__ float gelu_t(float x) {
    float t = tanhf(0.7978845608028654f * (x + 0.044715f * x * x * x));
    return 0.5f * x * (1.0f + t);
}

__global__ __launch_bounds__(256, 2)
void mma_gemm_kernel(const float* __restrict__ A, const float* __restrict__ Bg,
                     const float* __restrict__ Res, float* __restrict__ C,
                     int M, int N, int K, int mode) {
    extern __shared__ float smem[];
    float* stage[2] = { smem, smem + STAGE_FLOATS };

    const int tid  = threadIdx.x;
    const int lane = tid & 31;
    const int warp = tid >> 5;
    const int gid  = lane >> 2;
    const int tg   = lane & 3;
    const int wm   = warp >> 1;
    const int wn   = warp & 1;

    const int bm = blockIdx.y * BM;
    const int bn = blockIdx.x * BN;

    const int arow = tid >> 3;
    const int acol = (tid & 7) * 4;
    const int brow = tid >> 5;
    const int bcol = (tid & 31) * 4;

    float acc[2][8][4];
    #pragma unroll
    for (int i = 0; i < 2; i++)
        #pragma unroll
        for (int j = 0; j < 8; j++)
            #pragma unroll
            for (int l = 0; l < 4; l++) acc[i][j][l] = 0.f;

    const int ntiles = K / BK;

    #define ISSUE_TILE(t, buf) do {                                            \
        float* As_ = stage[buf];                                               \
        float* Bs_ = stage[buf] + BM * ASTRIDE;                                \
        int k0_ = (t) * BK;                                                    \
        _Pragma("unroll")                                                      \
        for (int i = 0; i < 4; i++)                                            \
            cp16(&As_[(arow + 32 * i) * ASTRIDE + acol],                       \
                 &A[(size_t)(bm + arow + 32 * i) * K + k0_ + acol]);           \
        _Pragma("unroll")                                                      \
        for (int i = 0; i < 4; i++)                                            \
            cp16(&Bs_[(brow + 8 * i) * BSTRIDE + bcol],                        \
                 &Bg[(size_t)(k0_ + brow + 8 * i) * N + bn + bcol]);           \
        asm volatile("cp.async.commit_group;");                                \
    } while (0)

    ISSUE_TILE(0, 0);

    for (int t = 0; t < ntiles; t++) {
        if (t + 1 < ntiles) {
            ISSUE_TILE(t + 1, (t + 1) & 1);
            asm volatile("cp.async.wait_group 1;");
        } else {
            asm volatile("cp.async.wait_group 0;");
        }
        __syncthreads();

        const float* As = stage[t & 1];
        const float* Bs = stage[t & 1] + BM * ASTRIDE;

        #pragma unroll
        for (int ks = 0; ks < 4; ks++) {
            uint32_t af[2][4], bf[8][2];
            int col = ks * 8 + tg;
            #pragma unroll
            for (int mt = 0; mt < 2; mt++) {
                int r = wm * 32 + mt * 16 + gid;
                af[mt][0] = __float_as_uint(As[r * ASTRIDE + col]);
                af[mt][1] = __float_as_uint(As[(r + 8) * ASTRIDE + col]);
                af[mt][2] = __float_as_uint(As[r * ASTRIDE + col + 4]);
                af[mt][3] = __float_as_uint(As[(r + 8) * ASTRIDE + col + 4]);
            }
            #pragma unroll
            for (int nt = 0; nt < 8; nt++) {
                int c = wn * 64 + nt * 8 + gid;
                bf[nt][0] = __float_as_uint(Bs[(ks * 8 + tg) * BSTRIDE + c]);
                bf[nt][1] = __float_as_uint(Bs[(ks * 8 + tg + 4) * BSTRIDE + c]);
            }
            #pragma unroll
            for (int mt = 0; mt < 2; mt++)
                #pragma unroll
                for (int nt = 0; nt < 8; nt++)
                    mma_tf32(acc[mt][nt], af[mt], bf[nt]);
        }
        __syncthreads();
    }

    #pragma unroll
    for (int mt = 0; mt < 2; mt++) {
        #pragma unroll
        for (int nt = 0; nt < 8; nt++) {
            int m0 = bm + wm * 32 + mt * 16 + gid;
            int n0 = bn + wn * 64 + nt * 8 + tg * 2;
            float2 v0 = make_float2(acc[mt][nt][0], acc[mt][nt][1]);
            float2 v1 = make_float2(acc[mt][nt][2], acc[mt][nt][3]);
            if (mode == 1) {
                float2 r0 = *(const float2*)&Res[(size_t)m0 * N + n0];
                float2 r1 = *(const float2*)&Res[(size_t)(m0 + 8) * N + n0];
                v0.x += r0.x; v0.y += r0.y;
                v1.x += r1.x; v1.y += r1.y;
            } else if (mode == 2) {
                float2 r0 = *(const float2*)&Res[(size_t)m0 * N + n0];
                float2 r1 = *(const float2*)&Res[(size_t)(m0 + 8) * N + n0];
                v0.x = tf32r(gelu_t(r0.x) * v0.x);
                v0.y = tf32r(gelu_t(r0.y) * v0.y);
                v1.x = tf32r(gelu_t(r1.x) * v1.x);
                v1.y = tf32r(gelu_t(r1.y) * v1.y);
            }
            *(float2*)&C[(size_t)m0 * N + n0] = v0;
            *(float2*)&C[(size_t)(m0 + 8) * N + n0] = v1;
        }
    }
}

// =================== tiled sliding-window attention (512 thr, fused RoPE) ====
#define QT 64
#define KT 192
#define SSTR 196
#define ATTN_Q_FLOATS   (QT * DH_)
#define ATTN_K_FLOATS   (KT * DH_)
#define ATTN_S_FLOATS   (QT * SSTR)
#define ATTN_SMEM_FLOATS (ATTN_Q_FLOATS + 2 * ATTN_K_FLOATS + ATTN_S_FLOATS)
#define ATTN_SMEM_BYTES  (ATTN_SMEM_FLOATS * 4)

__device__ __forceinline__ int ksw(int row, int chunk) {
    return row * DH_ + 4 * (chunk ^ ((row >> 2) & 15));
}

// rotate one float4 pair (chunks c and c+8 of a 64-dim head) for position s
__device__ __forceinline__ void rope4(int s, int c, float4& lo, float4& hi) {
    #pragma unroll
    for (int l = 0; l < 4; l++) {
        int d = c * 4 + l;
        float w = (float)(2 * d) / (float)DH_;
        float inv_freq = 1.0f / powf(10000.0f, w);
        float ang = (float)s * inv_freq;
        float cs = cosf(ang);
        float sn = sinf(ang);
        float x1 = (&lo.x)[l];
        float x2 = (&hi.x)[l];
        (&lo.x)[l] = tf32r(x1 * cs - x2 * sn);
        (&hi.x)[l] = tf32r(x2 * cs + x1 * sn);
    }
}

__global__ __launch_bounds__(512, 1)
void attn_tile_kernel(const float* __restrict__ qkv, const int* __restrict__ pmask,
                      float* __restrict__ out) {
    extern __shared__ float sm[];
    float* Qs = sm;
    float* Ks = Qs + ATTN_Q_FLOATS;
    float* Vs = Ks + ATTN_K_FLOATS;
    float* Sc = Vs + ATTN_K_FLOATS;

    const int qt0 = blockIdx.x * QT;
    const int h   = blockIdx.y;
    const int b   = blockIdx.z;
    const int tid = threadIdx.x;

    // ---- Q load + RoPE (QT*8 = 512 items) ----
    {
        int r = tid >> 3, c = tid & 7;
        int s = qt0 + r;
        size_t base = (size_t)(b * S_ + s) * DQKV + h * DH_;
        float4 lo = *(const float4*)&qkv[base + c * 4];
        float4 hi = *(const float4*)&qkv[base + 32 + c * 4];
        rope4(s, c, lo, hi);
        *(float4*)&Qs[r * DH_ + c * 4] = lo;
        *(float4*)&Qs[r * DH_ + 32 + c * 4] = hi;
    }
    // ---- K (RoPE, swizzled) + V (plain) load; KT*8 = 1536 items ----
    for (int i = tid; i < KT * 8; i += 512) {
        int r = i >> 3, c = i & 7;
        int j = qt0 - WIN + r;
        float4 klo = make_float4(0.f,0.f,0.f,0.f), khi = klo, vlo = klo, vhi = klo;
        if (j >= 0 && j < S_) {
            size_t base = (size_t)(b * S_ + j) * DQKV + h * DH_;
            klo = *(const float4*)&qkv[base + DM_ + c * 4];
            khi = *(const float4*)&qkv[base + DM_ + 32 + c * 4];
            rope4(j, c, klo, khi);
            vlo = *(const float4*)&qkv[base + 2 * DM_ + c * 4];
            vhi = *(const float4*)&qkv[base + 2 * DM_ + 32 + c * 4];
            vlo.x = tf32r(vlo.x); vlo.y = tf32r(vlo.y); vlo.z = tf32r(vlo.z); vlo.w = tf32r(vlo.w);
            vhi.x = tf32r(vhi.x); vhi.y = tf32r(vhi.y); vhi.z = tf32r(vhi.z); vhi.w = tf32r(vhi.w);
        }
        *(float4*)&Ks[ksw(r, c)] = klo;
        *(float4*)&Ks[ksw(r, c + 8)] = khi;
        *(float4*)&Vs[r * DH_ + c * 4] = vlo;
        *(float4*)&Vs[r * DH_ + 32 + c * 4] = vhi;
    }
    __syncthreads();

    // ---- QK^T: 512 thr, thread = (tk 0..15, tq 0..31) -> 2q x 4k per panel ----
    {
        const int tk = tid & 15;
        const int tq = tid >> 4;            // 0..31
        #pragma unroll
        for (int kp = 0; kp < 3; kp++) {
            const int kbase = kp * 64 + tk * 4;
            float acc[2][4];
            #pragma unroll
            for (int i = 0; i < 2; i++)
                #pragma unroll
                for (int u = 0; u < 4; u++) acc[i][u] = 0.f;

            for (int c = 0; c < 16; c++) {
                float4 qv[2], kv[4];
                #pragma unroll
                for (int i = 0; i < 2; i++)
                    qv[i] = *(const float4*)&Qs[(tq * 2 + i) * DH_ + c * 4];
                #pragma unroll
                for (int u = 0; u < 4; u++)
                    kv[u] = *(const float4*)&Ks[ksw(kbase + u, c)];
                #pragma unroll
                for (int i = 0; i < 2; i++)
                    #pragma unroll
                    for (int u = 0; u < 4; u++)
                        acc[i][u] += qv[i].x * kv[u].x + qv[i].y * kv[u].y
                                   + qv[i].z * kv[u].z + qv[i].w * kv[u].w;
            }
            #pragma unroll
            for (int i = 0; i < 2; i++) {
                int ql = tq * 2 + i;
                int qg = qt0 + ql;
                #pragma unroll
                for (int u = 0; u < 4; u++) {
                    int kr = kbase + u;
                    int j = qt0 - WIN + kr;
                    float s;
                    if (j < 0 || j >= S_) {
                        s = -1e30f;
                    } else {
                        s = acc[i][u] * 0.125f;
                        int diff = j - qg;
                        if (diff > WIN || diff < -WIN) s -= 10000.0f;
                        if (pmask[b * S_ + j] == 0)    s -= 10000.0f;
                    }
                    Sc[ql * SSTR + kr] = s;
                }
            }
        }
    }
    __syncthreads();

    // ---- softmax: 8 threads / row ----
    {
        const int row = tid >> 3, sub = tid & 7;
        float m = -1e30f;
        for (int k = sub; k < KT; k += 8) m = fmaxf(m, Sc[row * SSTR + k]);
        m = fmaxf(m, __shfl_xor_sync(0xffffffffu, m, 1));
        m = fmaxf(m, __shfl_xor_sync(0xffffffffu, m, 2));
        m = fmaxf(m, __shfl_xor_sync(0xffffffffu, m, 4));
        float ssum = 0.f;
        for (int k = sub; k < KT; k += 8) {
            float e = expf(Sc[row * SSTR + k] - m);
            Sc[row * SSTR + k] = e;
            ssum += e;
        }
        ssum += __shfl_xor_sync(0xffffffffu, ssum, 1);
        ssum += __shfl_xor_sync(0xffffffffu, ssum, 2);
        ssum += __shfl_xor_sync(0xffffffffu, ssum, 4);
        for (int k = sub; k < KT; k += 8)
            Sc[row * SSTR + k] = tf32r(Sc[row * SSTR + k] / ssum);
    }
    __syncthreads();

    // ---- PV: lane covers d (conflict-free V), 2 q rows per thread ----
    {
        const int d4 = (tid & 15) * 4;       // 0..60
        const int q2 = (tid >> 4) * 2;       // 0..62
        float o[2][4];
        #pragma unroll
        for (int i = 0; i < 2; i++)
            #pragma unroll
            for (int u = 0; u < 4; u++) o[i][u] = 0.f;

        for (int k = 0; k < KT; k += 4) {
            float4 pv[2];
            #pragma unroll
            for (int i = 0; i < 2; i++)
                pv[i] = *(const float4*)&Sc[(q2 + i) * SSTR + k];
            #pragma unroll
            for (int kk = 0; kk < 4; kk++) {
                float4 vv = *(const float4*)&Vs[(k + kk) * DH_ + d4];
                #pragma unroll
                for (int i = 0; i < 2; i++) {
                    float p = (kk == 0) ? pv[i].x : (kk == 1) ? pv[i].y : (kk == 2) ? pv[i].z : pv[i].w;
                    o[i][0] += p * vv.x;
                    o[i][1] += p * vv.y;
                    o[i][2] += p * vv.z;
                    o[i][3] += p * vv.w;
                }
            }
        }
        #pragma unroll
        for (int i = 0; i < 2; i++) {
            float4 v = make_float4(tf32r(o[i][0]), tf32r(o[i][1]), tf32r(o[i][2]), tf32r(o[i][3]));
            *(float4*)&out[(size_t)(b * S_ + qt0 + q2 + i) * DM_ + h * DH_ + d4] = v;
        }
    }
}

// ---------------- launch ----------------
extern "C" void kernel_launch(void* const* d_in, const int* in_sizes, int n_in,
                              void* d_out, int out_size) {
    const float* x          = (const float*)d_in[0];
    const int*   pmask      = (const int*)  d_in[1];
    const float* w_qkv      = (const float*)d_in[2];
    const float* w_o        = (const float*)d_in[3];
    const float* gamma_attn = (const float*)d_in[4];
    const float* gamma_mlp  = (const float*)d_in[5];
    const float* w_i0       = (const float*)d_in[6];
    const float* w_i1       = (const float*)d_in[7];
    const float* w_mo       = (const float*)d_in[8];
    float* out = (float*)d_out;

    float *h, *qkv, *attn, *x1, *gate, *act;
    float *wqkv, *wo, *wi0, *wi1, *wmo;
    cudaGetSymbolAddress((void**)&h,    g_h);
    cudaGetSymbolAddress((void**)&qkv,  g_qkv);
    cudaGetSymbolAddress((void**)&attn, g_attn);
    cudaGetSymbolAddress((void**)&x1,   g_x1);
    cudaGetSymbolAddress((void**)&gate, g_gate);
    cudaGetSymbolAddress((void**)&act,  g_act);
    cudaGetSymbolAddress((void**)&wqkv, g_wqkv);
    cudaGetSymbolAddress((void**)&wo,   g_wo);
    cudaGetSymbolAddress((void**)&wi0,  g_wi0);
    cudaGetSymbolAddress((void**)&wi1,  g_wi1);
    cudaGetSymbolAddress((void**)&wmo,  g_wmo);

    cudaFuncSetAttribute(mma_gemm_kernel,
                         cudaFuncAttributeMaxDynamicSharedMemorySize, GEMM_SMEM_BYTES);
    cudaFuncSetAttribute(attn_tile_kernel,
                         cudaFuncAttributeMaxDynamicSharedMemorySize, ATTN_SMEM_BYTES);

    tf32cvt4_kernel<<<(DM_ * DQKV / 4 + 255) / 256, 256>>>((const float4*)w_qkv, (float4*)wqkv, DM_ * DQKV / 4);
    tf32cvt4_kernel<<<(DM_ * DM_  / 4 + 255) / 256, 256>>>((const float4*)w_o,   (float4*)wo,   DM_ * DM_  / 4);
    tf32cvt4_kernel<<<(DM_ * DI_  / 4 + 255) / 256, 256>>>((const float4*)w_i0,  (float4*)wi0,  DM_ * DI_  / 4);
    tf32cvt4_kernel<<<(DM_ * DI_  / 4 + 255) / 256, 256>>>((const float4*)w_i1,  (float4*)wi1,  DM_ * DI_  / 4);
    tf32cvt4_kernel<<<(DI_ * DM_  / 4 + 255) / 256, 256>>>((const float4*)w_mo,  (float4*)wmo,  DI_ * DM_  / 4);

    rmsnorm_kernel<<<ROWS, 256>>>(x, gamma_attn, h);
    mma_gemm_kernel<<<dim3(DQKV / BN, ROWS / BM), 256, GEMM_SMEM_BYTES>>>(
        h, wqkv, nullptr, qkv, ROWS, DQKV, DM_, 0);
    attn_tile_kernel<<<dim3(S_ / QT, H_, B_), 512, ATTN_SMEM_BYTES>>>(qkv, pmask, attn);
    mma_gemm_kernel<<<dim3(DM_ / BN, ROWS / BM), 256, GEMM_SMEM_BYTES>>>(
        attn, wo, x, x1, ROWS, DM_, DM_, 1);
    rmsnorm_kernel<<<ROWS, 256>>>(x1, gamma_mlp, h);
    mma_gemm_kernel<<<dim3(DI_ / BN, ROWS / BM), 256, GEMM_SMEM_BYTES>>>(
        h, wi0, nullptr, gate, ROWS, DI_, DM_, 0);
    // up-projection with fused gelu(gate) * up -> act
    mma_gemm_kernel<<<dim3(DI_ / BN, ROWS / BM), 256, GEMM_SMEM_BYTES>>>(
        h, wi1, gate, act, ROWS, DI_, DM_, 2);
    mma_gemm_kernel<<<dim3(DM_ / BN, ROWS / BM), 256, GEMM_SMEM_BYTES>>>(
        act, wmo, x1, out, ROWS, DM_, DI_, 1);
}